// round 17
// baseline (speedup 1.0000x reference)
#include <cuda_runtime.h>

#define CCH 512
#define TT  8192
#define PLANE (TT * CCH)

#define NCHUNK 128
#define CLEN   64      // output steps per chunk  (TT / NCHUNK)
#define BURN   144     // warm-up steps; measured err 2.38e-4 << 1e-3

#define NB_U   128     // U blocks in fused pre-kernel (scheduled first)

typedef unsigned long long u64;

__device__ __forceinline__ u64 fma2(u64 a, u64 b, u64 c) {
    u64 d; asm("fma.rn.f32x2 %0, %1, %2, %3;" : "=l"(d) : "l"(a), "l"(b), "l"(c)); return d;
}
__device__ __forceinline__ u64 mul2(u64 a, u64 b) {
    u64 d; asm("mul.rn.f32x2 %0, %1, %2;" : "=l"(d) : "l"(a), "l"(b)); return d;
}
__device__ __forceinline__ u64 pack2(float lo, float hi) {
    u64 d; asm("mov.b64 %0, {%1, %2};" : "=l"(d) : "f"(lo), "f"(hi)); return d;
}
__device__ __forceinline__ float2 unpack2(u64 a) {
    float2 r; asm("mov.b64 {%0, %1}, %2;" : "=f"(r.x), "=f"(r.y) : "l"(a)); return r;
}

// ---- static device scratch ----
__device__ float g_U[TT * 16];        // U[t,j] = b1[j] + W1^T y_t
__device__ u64   g_KVu[5 * PLANE];    // plane 0:(k0,k1) 1:(k2,k3) 2:(v0,v1) 3:(v2,v3) 4:(k4,v4); [m][t][c]
__device__ float g_dotT[PLANE];       // raw dot, t-major [t][c]

// ---------------- fused pre-pass: U (blocks 0..NB_U) + repack (rest) ----------------
__global__ void prepass(const float* __restrict__ K, const float* __restrict__ V,
                        const float* __restrict__ y,
                        const float* __restrict__ W1, const float* __restrict__ b1)
{
    const int tid = threadIdx.x;
    if (blockIdx.x < NB_U) {
        // ---- precompute U: thread (j, t4) computes U[4*t4 .. 4*t4+3][j] ----
        const int j  = tid & 15;
        const int t4 = blockIdx.x * 16 + (tid >> 4);
        const int t0 = t4 * 4;
        const float bj = b1[j];
        float a0 = bj, a1 = bj, a2 = bj, a3 = bj;
#pragma unroll 8
        for (int c = 0; c < CCH; c++) {
            const float4 yv = *(const float4*)&y[c * TT + t0];
            const float w = W1[c * 16 + j];
            a0 = fmaf(yv.x, w, a0);
            a1 = fmaf(yv.y, w, a1);
            a2 = fmaf(yv.z, w, a2);
            a3 = fmaf(yv.w, w, a3);
        }
        g_U[(t0 + 0) * 16 + j] = a0;
        g_U[(t0 + 1) * 16 + j] = a1;
        g_U[(t0 + 2) * 16 + j] = a2;
        g_U[(t0 + 3) * 16 + j] = a3;
    } else {
        // ---- repack K,V ----
        const int idx = (blockIdx.x - NB_U) * blockDim.x + tid;   // t*512 + c
        const long b = (long)idx * 5;
        g_KVu[0 * PLANE + idx] = pack2(K[b + 0], K[b + 1]);
        g_KVu[1 * PLANE + idx] = pack2(K[b + 2], K[b + 3]);
        g_KVu[2 * PLANE + idx] = pack2(V[b + 0], V[b + 1]);
        g_KVu[3 * PLANE + idx] = pack2(V[b + 2], V[b + 3]);
        g_KVu[4 * PLANE + idx] = pack2(K[b + 4], V[b + 4]);
    }
}

// ---------------- chunked recurrence + fused transpose epilogue ----------------
// Chunk i: outputs t in [out0, out0+CLEN), warm-up from max(0, out0-BURN) with
// zero state (measured truncation 2.38e-4 << 1e-3). After its final step, the
// CTA transposes+scales its own 64x512 slab from L2-hot g_dotT into out.
__global__ __launch_bounds__(512, 1)
void rca_kernel(const float* __restrict__ W1,
                const float* __restrict__ W2,
                const float* __restrict__ b2,
                float* __restrict__ out)
{
    __shared__ float sdot[CCH];
    __shared__ float ss[16];
    __shared__ __align__(16) float sh[16];
    __shared__ float siv[CLEN];            // inv for owned steps
    __shared__ float tile64[64][33];       // epilogue transpose tile

    const int tid  = threadIdx.x;
    const int wid  = tid >> 5;
    const int lane = tid & 31;

    const int out0    = blockIdx.x * CLEN;
    const int t_begin = (out0 >= BURN) ? (out0 - BURN) : 0;
    const int t_end   = out0 + CLEN;

    // B-phase channel mapping: lane handles c = 4*lane + 128*ii + k (conflict-free LDS.128)
    float w1r[16];
#pragma unroll
    for (int ii = 0; ii < 4; ii++)
#pragma unroll
        for (int k = 0; k < 4; k++)
            w1r[4 * ii + k] = W1[(4 * lane + 128 * ii + k) * 16 + wid];

    float w2r[16];
#pragma unroll
    for (int j = 0; j < 16; j++) w2r[j] = W2[j * CCH + tid];
    const float b2c = b2[tid];

    // packed EMA state
    u64 e01 = pack2(0.f, 0.f), e23 = pack2(0.f, 0.f);
    float e4 = 0.f;
    const u64 c95 = pack2(0.95f, 0.95f);

    // depth-3 prefetch
    u64  kv[3][5];
    float ub[3];
#pragma unroll
    for (int i = 0; i < 3; i++) {
        const int tp  = (t_begin + i < TT) ? (t_begin + i) : (TT - 1);
        const int idx = tp * CCH + tid;
#pragma unroll
        for (int m = 0; m < 5; m++) kv[i][m] = g_KVu[m * PLANE + idx];
        ub[i] = g_U[tp * 16 + wid];
    }

    sdot[tid] = 0.f;
    if (tid < 16) ss[tid] = 0.f;
    __syncthreads();

    const float4* sd4 = (const float4*)sdot;

    for (int t0 = t_begin; t0 < t_end + 3; t0 += 3) {
#pragma unroll
        for (int i = 0; i < 3; i++) {
            const int t = t0 + i;

            // ---------- B: g[wid] = sum_c dot_prev[c]*W1[c,wid]; s = sum ema^2 ----------
            float g0 = 0.f, g1 = 0.f, g2 = 0.f, g3 = 0.f;
#pragma unroll
            for (int ii = 0; ii < 4; ii++) {
                const float4 d = sd4[lane + 32 * ii];
                g0 = fmaf(d.x, w1r[4 * ii + 0], g0);
                g1 = fmaf(d.y, w1r[4 * ii + 1], g1);
                g2 = fmaf(d.z, w1r[4 * ii + 2], g2);
                g3 = fmaf(d.w, w1r[4 * ii + 3], g3);
            }
            float g = (g0 + g1) + (g2 + g3);
            float s = ss[lane & 15];
            // interleaved butterflies: g (5 rounds), s (4 rounds)
            g += __shfl_xor_sync(0xffffffffu, g, 16);
            s += __shfl_xor_sync(0xffffffffu, s, 8);
            g += __shfl_xor_sync(0xffffffffu, g, 8);
            s += __shfl_xor_sync(0xffffffffu, s, 4);
            g += __shfl_xor_sync(0xffffffffu, g, 4);
            s += __shfl_xor_sync(0xffffffffu, s, 2);
            g += __shfl_xor_sync(0xffffffffu, g, 2);
            s += __shfl_xor_sync(0xffffffffu, s, 1);
            g += __shfl_xor_sync(0xffffffffu, g, 1);

            const float inv = rsqrtf(fmaxf(s, 1e-37f));
            if (lane == 0) {
                sh[wid] = fmaxf(fmaf(g, inv, ub[i]), 0.f);
                if (wid == 0 && t > out0) siv[t - 1 - out0] = inv;   // owned steps only
            }
            if (t == t_end) goto epilogue;   // uniform per CTA

            __syncthreads();   // sh visible; ss/sdot reads done before A writes

            // ---------- C: q[c] = b2[c] + sum_j h[j]*W2[j,c] ----------
            {
            const float4 h0 = *(const float4*)&sh[0];
            const float4 h1 = *(const float4*)&sh[4];
            const float4 h2 = *(const float4*)&sh[8];
            const float4 h3 = *(const float4*)&sh[12];
            float q0 = b2c, q1 = 0.f, q2 = 0.f, q3 = 0.f;
            q0 = fmaf(h0.x, w2r[0],  q0); q1 = fmaf(h0.y, w2r[1],  q1);
            q2 = fmaf(h0.z, w2r[2],  q2); q3 = fmaf(h0.w, w2r[3],  q3);
            q0 = fmaf(h1.x, w2r[4],  q0); q1 = fmaf(h1.y, w2r[5],  q1);
            q2 = fmaf(h1.z, w2r[6],  q2); q3 = fmaf(h1.w, w2r[7],  q3);
            q0 = fmaf(h2.x, w2r[8],  q0); q1 = fmaf(h2.y, w2r[9],  q1);
            q2 = fmaf(h2.z, w2r[10], q2); q3 = fmaf(h2.w, w2r[11], q3);
            q0 = fmaf(h3.x, w2r[12], q0); q1 = fmaf(h3.y, w2r[13], q1);
            q2 = fmaf(h3.z, w2r[14], q2); q3 = fmaf(h3.w, w2r[15], q3);
            const float qm = 0.05f * ((q0 + q1) + (q2 + q3));

            // ---------- A: packed ema update, dot, sp ----------
            const u64 qm2 = pack2(qm, qm);
            e01 = fma2(e01, c95, mul2(kv[i][0], qm2));
            e23 = fma2(e23, c95, mul2(kv[i][1], qm2));
            const float2 k4v4 = unpack2(kv[i][4]);
            e4 = fmaf(0.95f, e4, qm * k4v4.x);

            u64 d2 = mul2(e01, kv[i][2]);
            d2 = fma2(e23, kv[i][3], d2);
            const float2 dd = unpack2(d2);
            float dot = dd.x + dd.y;
            dot = fmaf(e4, k4v4.y, dot);

            u64 s2 = mul2(e01, e01);
            s2 = fma2(e23, e23, s2);
            const float2 sv = unpack2(s2);
            float sp = sv.x + sv.y;
            sp = fmaf(e4, e4, sp);

            sdot[tid] = dot;
            if (t >= out0) g_dotT[t * CCH + tid] = dot;   // owned range only

            // prefetch t+3 into this slot
            {
                const int tn  = (t + 3 < TT) ? (t + 3) : (TT - 1);
                const int idx = tn * CCH + tid;
#pragma unroll
                for (int m = 0; m < 5; m++) kv[i][m] = g_KVu[m * PLANE + idx];
                ub[i] = g_U[tn * 16 + wid];
            }

            // warp-reduce sp -> ss[wid]
            sp += __shfl_xor_sync(0xffffffffu, sp, 16);
            sp += __shfl_xor_sync(0xffffffffu, sp, 8);
            sp += __shfl_xor_sync(0xffffffffu, sp, 4);
            sp += __shfl_xor_sync(0xffffffffu, sp, 2);
            sp += __shfl_xor_sync(0xffffffffu, sp, 1);
            if (lane == 0) ss[wid] = sp;
            }

            __syncthreads();   // sdot/ss visible for next B
        }
    }

epilogue:
    // ---- transpose + scale own slab: out[c*TT + t] = g_dotT[t][c] * siv[t-out0] ----
    __syncthreads();   // siv + this CTA's g_dotT writes visible to all its threads
    {
        const int tx = lane;            // 0..31
        const int ty = wid;             // 0..15
        const int t64 = tid & 63;       // 0..63 (t within slab)
        const int cq  = tid >> 6;       // 0..7  (c sub-row)
        for (int c0 = 0; c0 < CCH; c0 += 32) {
#pragma unroll
            for (int r = ty; r < CLEN; r += 16)
                tile64[r][tx] = g_dotT[(out0 + r) * CCH + (c0 + tx)] * siv[r];
            __syncthreads();
#pragma unroll
            for (int r2 = cq; r2 < 32; r2 += 8)
                out[(long)(c0 + r2) * TT + out0 + t64] = tile64[t64][r2];
            __syncthreads();
        }
    }
}

extern "C" void kernel_launch(void* const* d_in, const int* in_sizes, int n_in,
                              void* d_out, int out_size) {
    const float* y  = (const float*)d_in[0];
    const float* Kp = (const float*)d_in[1];
    const float* Vp = (const float*)d_in[2];
    const float* W1 = (const float*)d_in[3];
    const float* b1 = (const float*)d_in[4];
    const float* W2 = (const float*)d_in[5];
    const float* b2 = (const float*)d_in[6];
    float* out = (float*)d_out;

    prepass<<<NB_U + PLANE / 256, 256>>>(Kp, Vp, y, W1, b1);
    rca_kernel<<<NCHUNK, 512>>>(W1, W2, b2, out);
}